// round 12
// baseline (speedup 1.0000x reference)
#include <cuda_runtime.h>
#include <cuda_bf16.h>
#include <math.h>

#define HN 256
#define VN 8192
#define SN 4096
#define LDA 40          // bf16 row stride in smem tiles (80B -> ldmatrix conflict-free)
#define KC 32           // k-chunk
#define GRID 296        // 2 CTAs x 148 SMs, all resident -> grid barrier safe

// ---------------- device scratch ----------------
__device__ float g_a[HN];                 // Wa*hidden + Wa_b + Ua_b
__device__ float g_u[3 * HN];             // Uz*y+b, Ur*y+b, Uh*y+b
__device__ float g_expE[SN];              // exp(attention logits) (|E|<~5, no max needed)
__device__ float g_sumexp;
__device__ float g_Ci[2 * HN];            // UNNORMALIZED context: scaled by 1/sumexp at use
__device__ float g_zr[2 * HN];
__device__ float g_hid[HN];
__device__ float g_logits[VN];
__device__ float g_vsum;
__device__ int   g_bar;                   // grid barrier counter (reset in k_pre)
__device__ int   g_ticket;                // work-pool ticket   (reset in k_pre)
__device__ __nv_bfloat16 g_Ua16[HN * 512];

__device__ __forceinline__ float warpSum(float v) {
#pragma unroll
    for (int o = 16; o; o >>= 1) v += __shfl_down_sync(0xffffffffu, v, o);
    return v;
}
__device__ __forceinline__ float blockSum256(float v, float* sred) {
    int t = threadIdx.x;
    v = warpSum(v);
    if ((t & 31) == 0) sred[t >> 5] = v;
    __syncthreads();
    float r = 0.f;
    if (t < 8) {
        r = sred[t];
#pragma unroll
        for (int o = 4; o; o >>= 1) r += __shfl_down_sync(0xffu, r, o);
    }
    return r;
}
__device__ __forceinline__ unsigned pkbf(float lo, float hi) {
    __nv_bfloat162 h(__float2bfloat16(lo), __float2bfloat16(hi));
    return *reinterpret_cast<unsigned*>(&h);
}
__device__ __forceinline__ float tanh_fast(float x) {
    float y; asm("tanh.approx.f32 %0, %1;" : "=f"(y) : "f"(x)); return y;
}
__device__ __forceinline__ void ldm_x4(unsigned& r0, unsigned& r1, unsigned& r2, unsigned& r3,
                                       unsigned addr) {
    asm volatile("ldmatrix.sync.aligned.m8n8.x4.shared.b16 {%0,%1,%2,%3}, [%4];"
                 : "=r"(r0), "=r"(r1), "=r"(r2), "=r"(r3) : "r"(addr));
}
__device__ __forceinline__ void mma_bf16(float* c, unsigned a0, unsigned a1, unsigned a2,
                                         unsigned a3, unsigned b0, unsigned b1) {
    asm volatile(
        "mma.sync.aligned.m16n8k16.row.col.f32.bf16.bf16.f32 "
        "{%0,%1,%2,%3},{%4,%5,%6,%7},{%8,%9},{%0,%1,%2,%3};"
        : "+f"(c[0]), "+f"(c[1]), "+f"(c[2]), "+f"(c[3])
        : "r"(a0), "r"(a1), "r"(a2), "r"(a3), "r"(b0), "r"(b1));
}
__device__ __forceinline__ void gsync(int target) {
    __syncthreads();
    if (threadIdx.x == 0) {
        __threadfence();
        atomicAdd(&g_bar, 1);
        int v;
        do {
            asm volatile("ld.acquire.gpu.b32 %0, [%1];" : "=r"(v) : "l"(&g_bar) : "memory");
        } while (v < target);
    }
    __syncthreads();
}
__device__ __forceinline__ void pf_l2(const void* p) {
    asm volatile("prefetch.global.L2 [%0];" :: "l"(p));
}
__device__ __forceinline__ void pf_range(const char* base, size_t total, int bid, int t) {
    size_t per = (((total + GRID - 1) / GRID) + 127) & ~(size_t)127;
    size_t s = (size_t)bid * per;
    size_t e = s + per; if (e > total) e = total;
    for (size_t o = s + (size_t)t * 128; o < e; o += 256u * 128u) pf_l2(base + o);
}

// ---------------- K_pre: init + Wa GEMV (warp-per-row) + Ua->bf16 ----------
__global__ void __launch_bounds__(256) k_pre(const float* __restrict__ hidden,
                                             const float* __restrict__ Waw,
                                             const float* __restrict__ Wab,
                                             const float* __restrict__ Uab,
                                             const float* __restrict__ Uaw) {
    int b = blockIdx.x, t = threadIdx.x;
    int lane = t & 31, wid = t >> 5;

    if (b == 0) {  // init scratch
        g_Ci[t] = 0.f; g_Ci[t + HN] = 0.f;
        if (t == 0) { g_sumexp = 0.f; g_vsum = 0.f; g_bar = 0; g_ticket = 0; }
    }

    // Ua convert: 64 blocks x 2048 elems
    {
        int base = b * 2048 + t * 8;
        float4 v0 = *reinterpret_cast<const float4*>(Uaw + base);
        float4 v1 = *reinterpret_cast<const float4*>(Uaw + base + 4);
        uint4 o;
        o.x = pkbf(v0.x, v0.y); o.y = pkbf(v0.z, v0.w);
        o.z = pkbf(v1.x, v1.y); o.w = pkbf(v1.z, v1.w);
        *reinterpret_cast<uint4*>(g_Ua16 + base) = o;
    }

    // Wa GEMV: warp per row, rows 0..255 over 512 warps
    int row = b * 8 + wid;
    if (row < HN) {
        const float4* w4 = reinterpret_cast<const float4*>(Waw + (size_t)row * HN);
        const float4* h4 = reinterpret_cast<const float4*>(hidden);
        float4 a0 = w4[lane], b0 = h4[lane], a1 = w4[lane + 32], b1 = h4[lane + 32];
        float v = a0.x * b0.x + a0.y * b0.y + a0.z * b0.z + a0.w * b0.w
                + a1.x * b1.x + a1.y * b1.y + a1.z * b1.z + a1.w * b1.w;
        v = warpSum(v);
        if (lane == 0) g_a[row] = v + Wab[row] + Uab[row];
    }
}

// ---------------- K_mega: persistent kernel, everything else ----------------
__global__ void __launch_bounds__(256, 2) k_mega(
        const int* __restrict__ tok, const float* __restrict__ emb,
        const float* __restrict__ hidden, const float* __restrict__ enc,
        const float* __restrict__ Vaw, const float* __restrict__ Vab,
        const float* __restrict__ Uzw, const float* __restrict__ Uzb,
        const float* __restrict__ Urw, const float* __restrict__ Urb,
        const float* __restrict__ Uhw, const float* __restrict__ Uhb,
        const float* __restrict__ Wzw, const float* __restrict__ Wzb,
        const float* __restrict__ Wrw, const float* __restrict__ Wrb,
        const float* __restrict__ Czw, const float* __restrict__ Czb,
        const float* __restrict__ Crw, const float* __restrict__ Crb,
        const float* __restrict__ Whw, const float* __restrict__ Whb,
        const float* __restrict__ Chw, const float* __restrict__ Chb,
        const float* __restrict__ Vw,  const float* __restrict__ Vb,
        float* __restrict__ out, float* __restrict__ out_hidden,
        float* __restrict__ aij) {
    __shared__ __align__(16) __nv_bfloat16 As[32 * LDA];
    __shared__ __align__(16) __nv_bfloat16 Bs[256 * LDA];
    __shared__ float sE[32];
    __shared__ float s_ex[32];
    __shared__ float sred[8];
    __shared__ int   s_ticket;
    __shared__ __align__(16) float sh2[HN];
    __shared__ float s_vsum;

    int bid = blockIdx.x, t = threadIdx.x;
    int lane = t & 31, wid = t >> 5;

    // ======================= PHASE A: ticket work pool =======================
    // tickets 0..127: attention tiles (32 s-rows)   128..895: U-GEMV rows
    for (;;) {
        __syncthreads();
        if (t == 0) s_ticket = atomicAdd(&g_ticket, 1);
        __syncthreads();
        int w = s_ticket;
        if (w >= 896) break;

        if (w >= 128) {
            // ---- U GEMV: g_u[g*HN+h] = U[h,:] . emb[tok] + b ----
            int idx = w - 128, g = idx >> 8, h = idx & 255;
            const float* W = (g == 0) ? Uzw : ((g == 1) ? Urw : Uhw);
            const float* B = (g == 0) ? Uzb : ((g == 1) ? Urb : Uhb);
            const float4* y = reinterpret_cast<const float4*>(emb + (size_t)tok[0] * VN);
            const float4* wv = reinterpret_cast<const float4*>(W + (size_t)h * VN);
            float v = 0.f;
#pragma unroll
            for (int i = 0; i < VN / 4; i += 256) {
                float4 a = wv[i + t], c = y[i + t];
                v = fmaf(a.x, c.x, fmaf(a.y, c.y, fmaf(a.z, c.z, fmaf(a.w, c.w, v))));
            }
            float r = blockSum256(v, sred);
            if (t == 0) g_u[g * HN + h] = r + B[h];
            continue;
        }

        // ---- attention tile: 32 s-rows via bf16 MMA (+ unnormalized Ci partial)
        int s0 = w * 32;
        int sg = wid & 1;        // s-group (16 rows)
        int hg = wid >> 1;       // h-group (64 cols)
        if (t < 32) sE[t] = 0.f;

        float acc[8][4];
#pragma unroll
        for (int nt = 0; nt < 8; nt++)
#pragma unroll
            for (int j = 0; j < 4; j++) acc[nt][j] = 0.f;

        unsigned as_base = (unsigned)__cvta_generic_to_shared(As);
        unsigned bs_base = (unsigned)__cvta_generic_to_shared(Bs);
        unsigned a_addr = as_base + ((sg * 16 + (lane & 15)) * LDA + (lane >> 4) * 8) * 2;
        unsigned b_addr0 = bs_base + ((hg * 64 + (lane & 15)) * LDA + (lane >> 4) * 8) * 2;
        int ar = t >> 3, akc = (t & 7) * 4;

        // register double-buffer: prologue load of chunk 0
        float4 enc_v = *reinterpret_cast<const float4*>(enc + (size_t)(s0 + ar) * 512 + akc);
        const uint4* usrc = reinterpret_cast<const uint4*>(g_Ua16 + (size_t)t * 512);
        uint4 ua0 = usrc[0], ua1 = usrc[1], ua2 = usrc[2], ua3 = usrc[3];

        for (int kb = 0; kb < 512; kb += KC) {
            __syncthreads();                 // consumers done with previous chunk
            {   // store staged regs: enc fp32 -> bf16 (32 x 32)
                uint2 p; p.x = pkbf(enc_v.x, enc_v.y); p.y = pkbf(enc_v.z, enc_v.w);
                *reinterpret_cast<uint2*>(As + ar * LDA + akc) = p;
            }
            {   // store staged Ua16 row t (64B)
                uint4* dst = reinterpret_cast<uint4*>(Bs + t * LDA);
                dst[0] = ua0; dst[1] = ua1; dst[2] = ua2; dst[3] = ua3;
            }
            if (kb + KC < 512) {             // issue next-chunk loads: in flight during MMA
                enc_v = *reinterpret_cast<const float4*>(
                    enc + (size_t)(s0 + ar) * 512 + kb + KC + akc);
                const uint4* s2 = reinterpret_cast<const uint4*>(
                    g_Ua16 + (size_t)t * 512 + kb + KC);
                ua0 = s2[0]; ua1 = s2[1]; ua2 = s2[2]; ua3 = s2[3];
            }
            __syncthreads();                 // staging visible
#pragma unroll
            for (int ks = 0; ks < 2; ks++) {
                unsigned a0, a1, a2, a3;
                ldm_x4(a0, a1, a2, a3, a_addr + ks * 32);
#pragma unroll
                for (int ntp = 0; ntp < 4; ntp++) {
                    unsigned r0, r1, r2, r3;
                    ldm_x4(r0, r1, r2, r3, b_addr0 + ntp * 16 * LDA * 2 + ks * 32);
                    mma_bf16(acc[2 * ntp],     a0, a1, a2, a3, r0, r2);
                    mma_bf16(acc[2 * ntp + 1], a0, a1, a2, a3, r1, r3);
                }
            }
        }

        {   // epilogue: E[s] partials = sum_h Va[h]*tanh(P + g_a[h])
            int g = lane >> 2, tig = lane & 3;
            float p0 = 0.f, p1 = 0.f;
#pragma unroll
            for (int nt = 0; nt < 8; nt++) {
                int c0 = hg * 64 + nt * 8 + 2 * tig;
                float ga0 = g_a[c0], ga1 = g_a[c0 + 1];
                float va0 = Vaw[c0], va1 = Vaw[c0 + 1];
                p0 += va0 * tanh_fast(acc[nt][0] + ga0) + va1 * tanh_fast(acc[nt][1] + ga1);
                p1 += va0 * tanh_fast(acc[nt][2] + ga0) + va1 * tanh_fast(acc[nt][3] + ga1);
            }
            p0 += __shfl_xor_sync(0xffffffffu, p0, 1); p0 += __shfl_xor_sync(0xffffffffu, p0, 2);
            p1 += __shfl_xor_sync(0xffffffffu, p1, 1); p1 += __shfl_xor_sync(0xffffffffu, p1, 2);
            if (tig == 0) {
                atomicAdd(&sE[sg * 16 + g], p0);
                atomicAdd(&sE[sg * 16 + g + 8], p1);
            }
        }
        __syncthreads();
        float ex = 0.f;
        if (t < 32) {
            ex = expf(sE[t] + Vab[0]);          // |E| <~ 5: no max needed
            g_expE[s0 + t] = ex;
            s_ex[t] = ex;
        }
        if (wid == 0) {
            float v = warpSum(ex);
            if (lane == 0) atomicAdd(&g_sumexp, v);
        }
        __syncthreads();
        {   // unnormalized Ci partial: thread t handles cols t and t+256
            const float* ep = enc + (size_t)s0 * 512;
            float a0 = 0.f, a1 = 0.f;
#pragma unroll 8
            for (int i = 0; i < 32; i++) {
                float e = s_ex[i];
                a0 = fmaf(e, ep[(size_t)i * 512 + t], a0);
                a1 = fmaf(e, ep[(size_t)i * 512 + 256 + t], a1);
            }
            atomicAdd(&g_Ci[t], a0);
            atomicAdd(&g_Ci[t + 256], a1);
        }
    }

    // prefetch phase C/D/E weights into L2 while stragglers finish
    pf_range((const char*)Vw,  (size_t)VN * HN * 4, bid, t);
    pf_range((const char*)Czw, (size_t)HN * 512 * 4, bid, t);
    pf_range((const char*)Crw, (size_t)HN * 512 * 4, bid, t);
    pf_range((const char*)Chw, (size_t)HN * 512 * 4, bid, t);
    pf_range((const char*)Whw, (size_t)HN * HN * 4, bid, t);
    pf_range((const char*)Wzw, (size_t)HN * HN * 4, bid, t);
    pf_range((const char*)Wrw, (size_t)HN * HN * 4, bid, t);

    gsync(1 * GRID);

    // ======================= PHASE C: z,r gates + aij ========================
    float inv = 1.0f / g_sumexp;
    {
        int gw = bid * 8 + wid;                  // warp per row, rows 0..511
        if (gw < 2 * HN) {
            int g = gw >> 8, h = gw & 255;
            const float* C  = g ? Crw : Czw;
            const float* Cb = g ? Crb : Czb;
            const float* W  = g ? Wrw : Wzw;
            const float* Wb = g ? Wrb : Wzb;
            const float4* c4  = reinterpret_cast<const float4*>(C + (size_t)h * 512);
            const float4* ci4 = reinterpret_cast<const float4*>(g_Ci);
            float vc = 0.f;
#pragma unroll
            for (int j = 0; j < 4; j++) {
                float4 a = c4[lane + 32 * j], c = ci4[lane + 32 * j];
                vc = fmaf(a.x, c.x, fmaf(a.y, c.y, fmaf(a.z, c.z, fmaf(a.w, c.w, vc))));
            }
            const float4* w4 = reinterpret_cast<const float4*>(W + (size_t)h * HN);
            const float4* h4 = reinterpret_cast<const float4*>(hidden);
            float vw = 0.f;
#pragma unroll
            for (int j = 0; j < 2; j++) {
                float4 a = w4[lane + 32 * j], c = h4[lane + 32 * j];
                vw = fmaf(a.x, c.x, fmaf(a.y, c.y, fmaf(a.z, c.z, fmaf(a.w, c.w, vw))));
            }
            float v = warpSum(vc * inv + vw);
            if (lane == 0) {
                float x = v + g_u[gw] + Cb[h] + Wb[h];
                g_zr[gw] = 1.f / (1.f + expf(-x));
            }
        }
        int idx = bid * 256 + t;                 // aij = expE / sumexp
        if (idx < SN) aij[idx] = g_expE[idx] * inv;
    }
    gsync(2 * GRID);

    // ======================= PHASE D: candidate + hidden_new =================
    {
        int h = bid * 8 + wid;                   // warp per row, rows 0..255
        if (h < HN) {
            const float4* wh4 = reinterpret_cast<const float4*>(Whw + (size_t)h * HN);
            const float4* ch4 = reinterpret_cast<const float4*>(Chw + (size_t)h * 512);
            const float4* zr4 = reinterpret_cast<const float4*>(g_zr);
            const float4* hh4 = reinterpret_cast<const float4*>(hidden);
            const float4* ci4 = reinterpret_cast<const float4*>(g_Ci);
            float vw = 0.f, vc = 0.f;
#pragma unroll
            for (int j = 0; j < 2; j++) {
                float4 a = wh4[lane + 32 * j];
                float4 r = zr4[64 + lane + 32 * j];   // r gate = g_zr[256..511]
                float4 hh = hh4[lane + 32 * j];
                vw = fmaf(a.x, r.x * hh.x, fmaf(a.y, r.y * hh.y,
                     fmaf(a.z, r.z * hh.z, fmaf(a.w, r.w * hh.w, vw))));
            }
#pragma unroll
            for (int j = 0; j < 4; j++) {
                float4 a = ch4[lane + 32 * j], c = ci4[lane + 32 * j];
                vc = fmaf(a.x, c.x, fmaf(a.y, c.y, fmaf(a.z, c.z, fmaf(a.w, c.w, vc))));
            }
            float v = warpSum(vw + vc * inv);
            if (lane == 0) {
                float c = tanhf(v + g_u[2 * HN + h] + Whb[h] + Chb[h]);
                float z = g_zr[h];
                float hn = (1.f - z) * c + z * hidden[h];
                g_hid[h] = hn;
                out_hidden[h] = hn;
            }
        }
    }
    gsync(3 * GRID);

    // ======================= PHASE E: vocab logits + vsum ====================
    sh2[t] = g_hid[t];
    if (t == 0) s_vsum = 0.f;
    __syncthreads();
    for (int row = bid * 8 + wid; row < VN; row += GRID * 8) {
        const float4* w  = reinterpret_cast<const float4*>(Vw + (size_t)row * HN);
        const float4* hv = reinterpret_cast<const float4*>(sh2);
        float4 w0 = w[lane], h0 = hv[lane], w1 = w[lane + 32], h1 = hv[lane + 32];
        float v = w0.x * h0.x + w0.y * h0.y + w0.z * h0.z + w0.w * h0.w
                + w1.x * h1.x + w1.y * h1.y + w1.z * h1.z + w1.w * h1.w;
        v = warpSum(v);
        if (lane == 0) {
            float l = v + Vb[row];
            g_logits[row] = l;
            atomicAdd(&s_vsum, expf(l));         // |logit| small: no max needed
        }
    }
    __syncthreads();
    if (t == 0) atomicAdd(&g_vsum, s_vsum);
    gsync(4 * GRID);

    // ======================= PHASE F: out = logits - lse =====================
    {
        float lse = logf(g_vsum);
        int i = bid * 256 + t;
        if (i < VN) out[i] = g_logits[i] - lse;
    }
}

// ---------------------------------------------------------------------------
extern "C" void kernel_launch(void* const* d_in, const int* in_sizes, int n_in,
                              void* d_out, int out_size) {
    (void)in_sizes; (void)n_in; (void)out_size;
    const int*   tok    = (const int*)  d_in[0];
    const float* hidden = (const float*)d_in[1];
    const float* enc    = (const float*)d_in[2];
    const float* emb    = (const float*)d_in[3];
    const float *Uzw = (const float*)d_in[4],  *Uzb = (const float*)d_in[5];
    const float *Wzw = (const float*)d_in[6],  *Wzb = (const float*)d_in[7];
    const float *Czw = (const float*)d_in[8],  *Czb = (const float*)d_in[9];
    const float *Urw = (const float*)d_in[10], *Urb = (const float*)d_in[11];
    const float *Wrw = (const float*)d_in[12], *Wrb = (const float*)d_in[13];
    const float *Crw = (const float*)d_in[14], *Crb = (const float*)d_in[15];
    const float *Uhw = (const float*)d_in[16], *Uhb = (const float*)d_in[17];
    const float *Whw = (const float*)d_in[18], *Whb = (const float*)d_in[19];
    const float *Chw = (const float*)d_in[20], *Chb = (const float*)d_in[21];
    const float *Uaw = (const float*)d_in[22], *Uab = (const float*)d_in[23];
    const float *Waw = (const float*)d_in[24], *Wab = (const float*)d_in[25];
    const float *Vaw = (const float*)d_in[26], *Vab = (const float*)d_in[27];
    const float *Vw  = (const float*)d_in[28], *Vb  = (const float*)d_in[29];

    float* out        = (float*)d_out;       // [VN] log_softmax
    float* out_hidden = out + VN;            // [HN] hidden_new
    float* aij        = out + VN + HN;       // [SN] attention weights

    k_pre<<<64, 256>>>(hidden, Waw, Wab, Uab, Uaw);
    k_mega<<<GRID, 256>>>(tok, emb, hidden, enc, Vaw, Vab,
                          Uzw, Uzb, Urw, Urb, Uhw, Uhb,
                          Wzw, Wzb, Wrw, Wrb,
                          Czw, Czb, Crw, Crb,
                          Whw, Whb, Chw, Chb,
                          Vw, Vb, out, out_hidden, aij);
}

// round 14
// speedup vs baseline: 1.0268x; 1.0268x over previous
#include <cuda_runtime.h>
#include <cuda_bf16.h>
#include <math.h>

#define HN 256
#define VN 8192
#define SN 4096
#define LDA 40            // Bs row stride in bf16 (80B: banks 20i%32 -> conflict-free)
#define LDE 520           // enc tile row stride in bf16 (1040B: banks 4i%32 -> conflict-free)
#define KC 32             // k-chunk
#define BSZ (256 * LDA * 2)                 // one Bs buffer: 20480 B
#define DSM_BYTES (32 * LDE * 2 + 2 * BSZ)  // 33280 + 40960 = 74240 B

// ---------------- device scratch ----------------
__device__ float g_a[HN];                 // Wa*hidden + Wa_b + Ua_b
__device__ float g_u[3 * HN];             // Uz*y+b, Ur*y+b, Uh*y+b
__device__ float g_expE[SN];              // exp(attention logits) (|E|<~5, no max needed)
__device__ float g_sumexp;
__device__ float g_Ci[2 * HN];            // UNNORMALIZED context: scaled by 1/sumexp at use
__device__ float g_zr[2 * HN];
__device__ float g_hid[HN];
__device__ float g_logits[VN];
__device__ float g_vsum;
__device__ int   g_bar;                   // grid barrier counter (reset in k_pre)
__device__ int   g_ticket;                // work-pool ticket   (reset in k_pre)
__device__ __nv_bfloat16 g_Ua16[HN * 512];

__device__ __forceinline__ float warpSum(float v) {
#pragma unroll
    for (int o = 16; o; o >>= 1) v += __shfl_down_sync(0xffffffffu, v, o);
    return v;
}
__device__ __forceinline__ float blockSum256(float v, float* sred) {
    int t = threadIdx.x;
    v = warpSum(v);
    if ((t & 31) == 0) sred[t >> 5] = v;
    __syncthreads();
    float r = 0.f;
    if (t < 8) {
        r = sred[t];
#pragma unroll
        for (int o = 4; o; o >>= 1) r += __shfl_down_sync(0xffu, r, o);
    }
    return r;
}
__device__ __forceinline__ unsigned pkbf(float lo, float hi) {
    __nv_bfloat162 h(__float2bfloat16(lo), __float2bfloat16(hi));
    return *reinterpret_cast<unsigned*>(&h);
}
__device__ __forceinline__ float tanh_fast(float x) {
    float y; asm("tanh.approx.f32 %0, %1;" : "=f"(y) : "f"(x)); return y;
}
__device__ __forceinline__ void ldm_x4(unsigned& r0, unsigned& r1, unsigned& r2, unsigned& r3,
                                       unsigned addr) {
    asm volatile("ldmatrix.sync.aligned.m8n8.x4.shared.b16 {%0,%1,%2,%3}, [%4];"
                 : "=r"(r0), "=r"(r1), "=r"(r2), "=r"(r3) : "r"(addr));
}
__device__ __forceinline__ void mma_bf16(float* c, unsigned a0, unsigned a1, unsigned a2,
                                         unsigned a3, unsigned b0, unsigned b1) {
    asm volatile(
        "mma.sync.aligned.m16n8k16.row.col.f32.bf16.bf16.f32 "
        "{%0,%1,%2,%3},{%4,%5,%6,%7},{%8,%9},{%0,%1,%2,%3};"
        : "+f"(c[0]), "+f"(c[1]), "+f"(c[2]), "+f"(c[3])
        : "r"(a0), "r"(a1), "r"(a2), "r"(a3), "r"(b0), "r"(b1));
}
__device__ __forceinline__ void cp16(unsigned dst, const void* src) {
    asm volatile("cp.async.cg.shared.global [%0], [%1], 16;" :: "r"(dst), "l"(src));
}
__device__ __forceinline__ void gsync(int mult) {
    __syncthreads();
    if (threadIdx.x == 0) {
        int target = mult * (int)gridDim.x;
        __threadfence();
        atomicAdd(&g_bar, 1);
        int v;
        do {
            asm volatile("ld.acquire.gpu.b32 %0, [%1];" : "=r"(v) : "l"(&g_bar) : "memory");
        } while (v < target);
    }
    __syncthreads();
}
__device__ __forceinline__ void pf_l2(const void* p) {
    asm volatile("prefetch.global.L2 [%0];" :: "l"(p));
}
__device__ __forceinline__ void pf_range(const char* base, size_t total, int bid, int t) {
    int nb = (int)gridDim.x;
    size_t per = (((total + nb - 1) / nb) + 127) & ~(size_t)127;
    size_t s = (size_t)bid * per;
    size_t e = s + per; if (e > total) e = total;
    for (size_t o = s + (size_t)t * 128; o < e; o += 256u * 128u) pf_l2(base + o);
}

// ---------------- K_pre: init + Wa GEMV (warp-per-row) + Ua->bf16 ----------
__global__ void __launch_bounds__(256) k_pre(const float* __restrict__ hidden,
                                             const float* __restrict__ Waw,
                                             const float* __restrict__ Wab,
                                             const float* __restrict__ Uab,
                                             const float* __restrict__ Uaw) {
    int b = blockIdx.x, t = threadIdx.x;
    int lane = t & 31, wid = t >> 5;

    if (b == 0) {  // init scratch
        g_Ci[t] = 0.f; g_Ci[t + HN] = 0.f;
        if (t == 0) { g_sumexp = 0.f; g_vsum = 0.f; g_bar = 0; g_ticket = 0; }
    }

    // Ua convert: 64 blocks x 2048 elems
    {
        int base = b * 2048 + t * 8;
        float4 v0 = *reinterpret_cast<const float4*>(Uaw + base);
        float4 v1 = *reinterpret_cast<const float4*>(Uaw + base + 4);
        uint4 o;
        o.x = pkbf(v0.x, v0.y); o.y = pkbf(v0.z, v0.w);
        o.z = pkbf(v1.x, v1.y); o.w = pkbf(v1.z, v1.w);
        *reinterpret_cast<uint4*>(g_Ua16 + base) = o;
    }

    // Wa GEMV: warp per row, rows 0..255 over 512 warps
    int row = b * 8 + wid;
    if (row < HN) {
        const float4* w4 = reinterpret_cast<const float4*>(Waw + (size_t)row * HN);
        const float4* h4 = reinterpret_cast<const float4*>(hidden);
        float4 a0 = w4[lane], b0 = h4[lane], a1 = w4[lane + 32], b1 = h4[lane + 32];
        float v = a0.x * b0.x + a0.y * b0.y + a0.z * b0.z + a0.w * b0.w
                + a1.x * b1.x + a1.y * b1.y + a1.z * b1.z + a1.w * b1.w;
        v = warpSum(v);
        if (lane == 0) g_a[row] = v + Wab[row] + Uab[row];
    }
}

// ---------------- K_mega: persistent kernel, everything else ----------------
__global__ void __launch_bounds__(256, 2) k_mega(
        const int* __restrict__ tok, const float* __restrict__ emb,
        const float* __restrict__ hidden, const float* __restrict__ enc,
        const float* __restrict__ Vaw, const float* __restrict__ Vab,
        const float* __restrict__ Uzw, const float* __restrict__ Uzb,
        const float* __restrict__ Urw, const float* __restrict__ Urb,
        const float* __restrict__ Uhw, const float* __restrict__ Uhb,
        const float* __restrict__ Wzw, const float* __restrict__ Wzb,
        const float* __restrict__ Wrw, const float* __restrict__ Wrb,
        const float* __restrict__ Czw, const float* __restrict__ Czb,
        const float* __restrict__ Crw, const float* __restrict__ Crb,
        const float* __restrict__ Whw, const float* __restrict__ Whb,
        const float* __restrict__ Chw, const float* __restrict__ Chb,
        const float* __restrict__ Vw,  const float* __restrict__ Vb,
        float* __restrict__ out, float* __restrict__ out_hidden,
        float* __restrict__ aij) {
    extern __shared__ __align__(16) char dsm[];
    __nv_bfloat16* s_encb = reinterpret_cast<__nv_bfloat16*>(dsm);          // 32 x LDE
    __nv_bfloat16* Bs     = reinterpret_cast<__nv_bfloat16*>(dsm + 32 * LDE * 2);

    __shared__ float sE[32];
    __shared__ float s_ex[32];
    __shared__ float sred[8];
    __shared__ int   s_ticket;
    __shared__ __align__(16) float sh2[HN];
    __shared__ float s_vsum;

    int bid = blockIdx.x, t = threadIdx.x;
    int lane = t & 31, wid = t >> 5;

    unsigned encb_base = (unsigned)__cvta_generic_to_shared(s_encb);
    unsigned bs_base   = (unsigned)__cvta_generic_to_shared(Bs);

    // ======================= PHASE A: ticket work pool =======================
    // tickets 0..127: attention tiles (32 s-rows)   128..895: U-GEMV rows
    for (;;) {
        __syncthreads();
        if (t == 0) s_ticket = atomicAdd(&g_ticket, 1);
        __syncthreads();
        int w = s_ticket;
        if (w >= 896) break;

        if (w >= 128) {
            // ---- U GEMV: g_u[g*HN+h] = U[h,:] . emb[tok] + b ----
            int idx = w - 128, g = idx >> 8, h = idx & 255;
            const float* W = (g == 0) ? Uzw : ((g == 1) ? Urw : Uhw);
            const float* B = (g == 0) ? Uzb : ((g == 1) ? Urb : Uhb);
            const float4* y = reinterpret_cast<const float4*>(emb + (size_t)tok[0] * VN);
            const float4* wv = reinterpret_cast<const float4*>(W + (size_t)h * VN);
            float v = 0.f;
#pragma unroll
            for (int i = 0; i < VN / 4; i += 256) {
                float4 a = wv[i + t], c = y[i + t];
                v = fmaf(a.x, c.x, fmaf(a.y, c.y, fmaf(a.z, c.z, fmaf(a.w, c.w, v))));
            }
            float r = blockSum256(v, sred);
            if (t == 0) g_u[g * HN + h] = r + B[h];
            continue;
        }

        // ---- attention tile: 32 s-rows via bf16 MMA (+ unnormalized Ci partial)
        int s0 = w * 32;
        int sg = wid & 1;        // s-group (16 rows)
        int hg = wid >> 1;       // h-group (64 cols)
        if (t < 32) sE[t] = 0.f;

        // kick off Bs chunk 0 via cp.async (fully overlapped with enc tile load)
        {
            const char* src = (const char*)(g_Ua16 + (size_t)t * 512);
            unsigned dst = bs_base + t * (LDA * 2);
            cp16(dst, src); cp16(dst + 16, src + 16);
            cp16(dst + 32, src + 32); cp16(dst + 48, src + 48);
            asm volatile("cp.async.commit_group;");
        }

        // load + convert the full 32x512 enc tile into smem bf16 (once per tile)
        // thread t: row = t>>3, 64 consecutive columns starting at (t&7)*64
        {
            int row = t >> 3, c0 = (t & 7) * 64;
            const float4* ev = reinterpret_cast<const float4*>(
                enc + (size_t)(s0 + row) * 512 + c0);
            __nv_bfloat16* dst = s_encb + row * LDE + c0;
#pragma unroll
            for (int j = 0; j < 4; j++) {
                float4 a = ev[4 * j], b2 = ev[4 * j + 1], c = ev[4 * j + 2], d = ev[4 * j + 3];
                uint4 o1, o2;
                o1.x = pkbf(a.x, a.y);  o1.y = pkbf(a.z, a.w);
                o1.z = pkbf(b2.x, b2.y); o1.w = pkbf(b2.z, b2.w);
                o2.x = pkbf(c.x, c.y);  o2.y = pkbf(c.z, c.w);
                o2.z = pkbf(d.x, d.y);  o2.w = pkbf(d.z, d.w);
                // ELEMENT offsets: 16 consecutive bf16 per j (8 + 8)
                *reinterpret_cast<uint4*>(dst + 16 * j)     = o1;
                *reinterpret_cast<uint4*>(dst + 16 * j + 8) = o2;
            }
        }

        float acc[8][4];
#pragma unroll
        for (int nt = 0; nt < 8; nt++)
#pragma unroll
            for (int j = 0; j < 4; j++) acc[nt][j] = 0.f;

        unsigned a_addr = encb_base + ((sg * 16 + (lane & 15)) * LDE + (lane >> 4) * 8) * 2;
        unsigned b_base = bs_base + ((hg * 64 + (lane & 15)) * LDA + (lane >> 4) * 8) * 2;

        __syncthreads();   // enc tile staged (Bs chunk 0 readiness via wait below)

        int buf = 0;
        for (int kb = 0; kb < 512; kb += KC, buf ^= 1) {
            if (kb + KC < 512) {   // issue next Bs chunk into other buffer
                const char* src = (const char*)(g_Ua16 + (size_t)t * 512 + kb + KC);
                unsigned dst = bs_base + (buf ^ 1) * BSZ + t * (LDA * 2);
                cp16(dst, src); cp16(dst + 16, src + 16);
                cp16(dst + 32, src + 32); cp16(dst + 48, src + 48);
                asm volatile("cp.async.commit_group;");
                asm volatile("cp.async.wait_group 1;");   // current chunk done
            } else {
                asm volatile("cp.async.wait_group 0;");
            }
            __syncthreads();       // Bs[buf] visible to all warps
            unsigned b_addr = b_base + buf * BSZ;
#pragma unroll
            for (int ks = 0; ks < 2; ks++) {
                unsigned a0, a1, a2, a3;
                ldm_x4(a0, a1, a2, a3, a_addr + (kb + ks * 16) * 2);
#pragma unroll
                for (int ntp = 0; ntp < 4; ntp++) {
                    unsigned r0, r1, r2, r3;
                    ldm_x4(r0, r1, r2, r3, b_addr + ntp * 16 * LDA * 2 + ks * 32);
                    mma_bf16(acc[2 * ntp],     a0, a1, a2, a3, r0, r2);
                    mma_bf16(acc[2 * ntp + 1], a0, a1, a2, a3, r1, r3);
                }
            }
            __syncthreads();       // all consumed Bs[buf] before it is overwritten
        }

        {   // epilogue: E[s] partials = sum_h Va[h]*tanh(P + g_a[h])
            int g = lane >> 2, tig = lane & 3;
            float p0 = 0.f, p1 = 0.f;
#pragma unroll
            for (int nt = 0; nt < 8; nt++) {
                int c0 = hg * 64 + nt * 8 + 2 * tig;
                float ga0 = g_a[c0], ga1 = g_a[c0 + 1];
                float va0 = Vaw[c0], va1 = Vaw[c0 + 1];
                p0 += va0 * tanh_fast(acc[nt][0] + ga0) + va1 * tanh_fast(acc[nt][1] + ga1);
                p1 += va0 * tanh_fast(acc[nt][2] + ga0) + va1 * tanh_fast(acc[nt][3] + ga1);
            }
            p0 += __shfl_xor_sync(0xffffffffu, p0, 1); p0 += __shfl_xor_sync(0xffffffffu, p0, 2);
            p1 += __shfl_xor_sync(0xffffffffu, p1, 1); p1 += __shfl_xor_sync(0xffffffffu, p1, 2);
            if (tig == 0) {
                atomicAdd(&sE[sg * 16 + g], p0);
                atomicAdd(&sE[sg * 16 + g + 8], p1);
            }
        }
        __syncthreads();
        float ex = 0.f;
        if (t < 32) {
            ex = expf(sE[t] + Vab[0]);          // |E| <~ 5: no max needed
            g_expE[s0 + t] = ex;
            s_ex[t] = ex;
        }
        if (wid == 0) {
            float v = warpSum(ex);
            if (lane == 0) atomicAdd(&g_sumexp, v);
        }
        __syncthreads();
        {   // unnormalized Ci partial: thread t handles cols t and t+256 (enc rows L2-hot)
            const float* ep = enc + (size_t)s0 * 512;
            float a0 = 0.f, a1 = 0.f;
#pragma unroll 8
            for (int i = 0; i < 32; i++) {
                float e = s_ex[i];
                a0 = fmaf(e, ep[(size_t)i * 512 + t], a0);
                a1 = fmaf(e, ep[(size_t)i * 512 + 256 + t], a1);
            }
            atomicAdd(&g_Ci[t], a0);
            atomicAdd(&g_Ci[t + 256], a1);
        }
    }

    // prefetch phase C/D/E weights into L2 while stragglers finish
    pf_range((const char*)Vw,  (size_t)VN * HN * 4, bid, t);
    pf_range((const char*)Czw, (size_t)HN * 512 * 4, bid, t);
    pf_range((const char*)Crw, (size_t)HN * 512 * 4, bid, t);
    pf_range((const char*)Chw, (size_t)HN * 512 * 4, bid, t);
    pf_range((const char*)Whw, (size_t)HN * HN * 4, bid, t);
    pf_range((const char*)Wzw, (size_t)HN * HN * 4, bid, t);
    pf_range((const char*)Wrw, (size_t)HN * HN * 4, bid, t);

    gsync(1);

    // ======================= PHASE C: z,r gates + aij ========================
    float inv = 1.0f / g_sumexp;
    {
        int gw = bid * 8 + wid;                  // warp per row, rows 0..511
        if (gw < 2 * HN) {
            int g = gw >> 8, h = gw & 255;
            const float* C  = g ? Crw : Czw;
            const float* Cb = g ? Crb : Czb;
            const float* W  = g ? Wrw : Wzw;
            const float* Wb = g ? Wrb : Wzb;
            const float4* c4  = reinterpret_cast<const float4*>(C + (size_t)h * 512);
            const float4* ci4 = reinterpret_cast<const float4*>(g_Ci);
            float vc = 0.f;
#pragma unroll
            for (int j = 0; j < 4; j++) {
                float4 a = c4[lane + 32 * j], c = ci4[lane + 32 * j];
                vc = fmaf(a.x, c.x, fmaf(a.y, c.y, fmaf(a.z, c.z, fmaf(a.w, c.w, vc))));
            }
            const float4* w4 = reinterpret_cast<const float4*>(W + (size_t)h * HN);
            const float4* h4 = reinterpret_cast<const float4*>(hidden);
            float vw = 0.f;
#pragma unroll
            for (int j = 0; j < 2; j++) {
                float4 a = w4[lane + 32 * j], c = h4[lane + 32 * j];
                vw = fmaf(a.x, c.x, fmaf(a.y, c.y, fmaf(a.z, c.z, fmaf(a.w, c.w, vw))));
            }
            float v = warpSum(vc * inv + vw);
            if (lane == 0) {
                float x = v + g_u[gw] + Cb[h] + Wb[h];
                g_zr[gw] = 1.f / (1.f + expf(-x));
            }
        }
        int idx = bid * 256 + t;                 // aij = expE / sumexp
        if (idx < SN) aij[idx] = g_expE[idx] * inv;
    }
    gsync(2);

    // ======================= PHASE D: candidate + hidden_new =================
    {
        int h = bid * 8 + wid;                   // warp per row, rows 0..255
        if (h < HN) {
            const float4* wh4 = reinterpret_cast<const float4*>(Whw + (size_t)h * HN);
            const float4* ch4 = reinterpret_cast<const float4*>(Chw + (size_t)h * 512);
            const float4* zr4 = reinterpret_cast<const float4*>(g_zr);
            const float4* hh4 = reinterpret_cast<const float4*>(hidden);
            const float4* ci4 = reinterpret_cast<const float4*>(g_Ci);
            float vw = 0.f, vc = 0.f;
#pragma unroll
            for (int j = 0; j < 2; j++) {
                float4 a = wh4[lane + 32 * j];
                float4 r = zr4[64 + lane + 32 * j];   // r gate = g_zr[256..511]
                float4 hh = hh4[lane + 32 * j];
                vw = fmaf(a.x, r.x * hh.x, fmaf(a.y, r.y * hh.y,
                     fmaf(a.z, r.z * hh.z, fmaf(a.w, r.w * hh.w, vw))));
            }
#pragma unroll
            for (int j = 0; j < 4; j++) {
                float4 a = ch4[lane + 32 * j], c = ci4[lane + 32 * j];
                vc = fmaf(a.x, c.x, fmaf(a.y, c.y, fmaf(a.z, c.z, fmaf(a.w, c.w, vc))));
            }
            float v = warpSum(vw + vc * inv);
            if (lane == 0) {
                float c = tanhf(v + g_u[2 * HN + h] + Whb[h] + Chb[h]);
                float z = g_zr[h];
                float hn = (1.f - z) * c + z * hidden[h];
                g_hid[h] = hn;
                out_hidden[h] = hn;
            }
        }
    }
    gsync(3);

    // ======================= PHASE E: vocab logits + vsum ====================
    sh2[t] = g_hid[t];
    if (t == 0) s_vsum = 0.f;
    __syncthreads();
    for (int row = bid * 8 + wid; row < VN; row += gridDim.x * 8) {
        const float4* w  = reinterpret_cast<const float4*>(Vw + (size_t)row * HN);
        const float4* hv = reinterpret_cast<const float4*>(sh2);
        float4 w0 = w[lane], h0 = hv[lane], w1 = w[lane + 32], h1 = hv[lane + 32];
        float v = w0.x * h0.x + w0.y * h0.y + w0.z * h0.z + w0.w * h0.w
                + w1.x * h1.x + w1.y * h1.y + w1.z * h1.z + w1.w * h1.w;
        v = warpSum(v);
        if (lane == 0) {
            float l = v + Vb[row];
            g_logits[row] = l;
            atomicAdd(&s_vsum, expf(l));         // |logit| small: no max needed
        }
    }
    __syncthreads();
    if (t == 0) atomicAdd(&g_vsum, s_vsum);
    gsync(4);

    // ======================= PHASE F: out = logits - lse =====================
    {
        float lse = logf(g_vsum);
        int i = bid * 256 + t;
        if (i < VN) out[i] = g_logits[i] - lse;
    }
}

// ---------------------------------------------------------------------------
extern "C" void kernel_launch(void* const* d_in, const int* in_sizes, int n_in,
                              void* d_out, int out_size) {
    (void)in_sizes; (void)n_in; (void)out_size;
    const int*   tok    = (const int*)  d_in[0];
    const float* hidden = (const float*)d_in[1];
    const float* enc    = (const float*)d_in[2];
    const float* emb    = (const float*)d_in[3];
    const float *Uzw = (const float*)d_in[4],  *Uzb = (const float*)d_in[5];
    const float *Wzw = (const float*)d_in[6],  *Wzb = (const float*)d_in[7];
    const float *Czw = (const float*)d_in[8],  *Czb = (const float*)d_in[9];
    const float *Urw = (const float*)d_in[10], *Urb = (const float*)d_in[11];
    const float *Wrw = (const float*)d_in[12], *Wrb = (const float*)d_in[13];
    const float *Crw = (const float*)d_in[14], *Crb = (const float*)d_in[15];
    const float *Uhw = (const float*)d_in[16], *Uhb = (const float*)d_in[17];
    const float *Whw = (const float*)d_in[18], *Whb = (const float*)d_in[19];
    const float *Chw = (const float*)d_in[20], *Chb = (const float*)d_in[21];
    const float *Uaw = (const float*)d_in[22], *Uab = (const float*)d_in[23];
    const float *Waw = (const float*)d_in[24], *Wab = (const float*)d_in[25];
    const float *Vaw = (const float*)d_in[26], *Vab = (const float*)d_in[27];
    const float *Vw  = (const float*)d_in[28], *Vb  = (const float*)d_in[29];

    float* out        = (float*)d_out;       // [VN] log_softmax
    float* out_hidden = out + VN;            // [HN] hidden_new
    float* aij        = out + VN + HN;       // [SN] attention weights

    // host-side config: runs once at capture time, free at graph replay
    static int grid = 0;
    if (grid == 0) {
        cudaFuncSetAttribute(k_mega, cudaFuncAttributeMaxDynamicSharedMemorySize, DSM_BYTES);
        int dev = 0; cudaGetDevice(&dev);
        int sms = 148;
        cudaDeviceGetAttribute(&sms, cudaDevAttrMultiProcessorCount, dev);
        int nb = 1;
        cudaOccupancyMaxActiveBlocksPerMultiprocessor(&nb, k_mega, 256, DSM_BYTES);
        if (nb < 1) nb = 1;
        if (nb > 2) nb = 2;
        grid = sms * nb;          // all CTAs wave-1 resident -> grid barrier safe
    }

    k_pre<<<64, 256>>>(hidden, Waw, Wab, Uab, Uaw);
    k_mega<<<grid, 256, DSM_BYTES>>>(tok, emb, hidden, enc, Vaw, Vab,
                                     Uzw, Uzb, Urw, Urb, Uhw, Uhb,
                                     Wzw, Wzb, Wrw, Wrb,
                                     Czw, Czb, Crw, Crb,
                                     Whw, Whb, Chw, Chb,
                                     Vw, Vb, out, out_hidden, aij);
}

// round 15
// speedup vs baseline: 1.1844x; 1.1535x over previous
#include <cuda_runtime.h>
#include <cuda_bf16.h>
#include <math.h>

#define HN 256
#define VN 8192
#define SN 4096
#define LDA 72            // Bs row stride in bf16 (144B: banks 4r%32 -> ldmatrix conflict-free)
#define LDE 520           // enc tile row stride in bf16 (1040B: banks 4i%32 -> conflict-free)
#define KC 64             // k-chunk (8 chunks -> 16 in-loop barriers per tile)
#define BSZ (256 * LDA * 2)                 // one Bs buffer: 36864 B
#define ENCB (32 * LDE * 2)                 // enc tile: 33280 B
#define DSM_BYTES (ENCB + 2 * BSZ + VN * 4) // 33280 + 73728 + 32768 = 139776 B

// ---------------- device scratch ----------------
__device__ float g_a[HN];                 // Wa*hidden + Wa_b + Ua_b
__device__ float g_u[3 * HN];             // Uz*y+b, Ur*y+b, Uh*y+b
__device__ float g_expE[SN];              // exp(attention logits) (|E|<~5, no max needed)
__device__ float g_sumexp;
__device__ float g_Ci[2 * HN];            // UNNORMALIZED context: scaled by 1/sumexp at use
__device__ float g_zr[2 * HN];
__device__ float g_hid[HN];
__device__ float g_logits[VN];
__device__ float g_vsum;
__device__ int   g_bar;                   // grid barrier counter (reset in k_pre)
__device__ int   g_ticket;                // work-pool ticket   (reset in k_pre)
__device__ __nv_bfloat16 g_Ua16[HN * 512];

__device__ __forceinline__ float warpSum(float v) {
#pragma unroll
    for (int o = 16; o; o >>= 1) v += __shfl_down_sync(0xffffffffu, v, o);
    return v;
}
__device__ __forceinline__ float blockSum256(float v, float* sred) {
    int t = threadIdx.x;
    v = warpSum(v);
    if ((t & 31) == 0) sred[t >> 5] = v;
    __syncthreads();
    float r = 0.f;
    if (t < 8) {
        r = sred[t];
#pragma unroll
        for (int o = 4; o; o >>= 1) r += __shfl_down_sync(0xffu, r, o);
    }
    return r;
}
__device__ __forceinline__ unsigned pkbf(float lo, float hi) {
    __nv_bfloat162 h(__float2bfloat16(lo), __float2bfloat16(hi));
    return *reinterpret_cast<unsigned*>(&h);
}
__device__ __forceinline__ float tanh_fast(float x) {
    float y; asm("tanh.approx.f32 %0, %1;" : "=f"(y) : "f"(x)); return y;
}
__device__ __forceinline__ void ldm_x4(unsigned& r0, unsigned& r1, unsigned& r2, unsigned& r3,
                                       unsigned addr) {
    asm volatile("ldmatrix.sync.aligned.m8n8.x4.shared.b16 {%0,%1,%2,%3}, [%4];"
                 : "=r"(r0), "=r"(r1), "=r"(r2), "=r"(r3) : "r"(addr));
}
__device__ __forceinline__ void mma_bf16(float* c, unsigned a0, unsigned a1, unsigned a2,
                                         unsigned a3, unsigned b0, unsigned b1) {
    asm volatile(
        "mma.sync.aligned.m16n8k16.row.col.f32.bf16.bf16.f32 "
        "{%0,%1,%2,%3},{%4,%5,%6,%7},{%8,%9},{%0,%1,%2,%3};"
        : "+f"(c[0]), "+f"(c[1]), "+f"(c[2]), "+f"(c[3])
        : "r"(a0), "r"(a1), "r"(a2), "r"(a3), "r"(b0), "r"(b1));
}
__device__ __forceinline__ void cp16(unsigned dst, const void* src) {
    asm volatile("cp.async.cg.shared.global [%0], [%1], 16;" :: "r"(dst), "l"(src));
}
__device__ __forceinline__ void gsync(int mult) {
    __syncthreads();
    if (threadIdx.x == 0) {
        int target = mult * (int)gridDim.x;
        __threadfence();
        atomicAdd(&g_bar, 1);
        int v;
        do {
            asm volatile("ld.acquire.gpu.b32 %0, [%1];" : "=r"(v) : "l"(&g_bar) : "memory");
        } while (v < target);
    }
    __syncthreads();
}
__device__ __forceinline__ void pf_l2(const void* p) {
    asm volatile("prefetch.global.L2 [%0];" :: "l"(p));
}
__device__ __forceinline__ void pf_range(const char* base, size_t total, int bid, int t) {
    int nb = (int)gridDim.x;
    size_t per = (((total + nb - 1) / nb) + 127) & ~(size_t)127;
    size_t s = (size_t)bid * per;
    size_t e = s + per; if (e > total) e = total;
    for (size_t o = s + (size_t)t * 128; o < e; o += 256u * 128u) pf_l2(base + o);
}

// ---------------- K_pre: init + Wa GEMV (warp-per-row) + Ua->bf16 ----------
__global__ void __launch_bounds__(256) k_pre(const float* __restrict__ hidden,
                                             const float* __restrict__ Waw,
                                             const float* __restrict__ Wab,
                                             const float* __restrict__ Uab,
                                             const float* __restrict__ Uaw) {
    int b = blockIdx.x, t = threadIdx.x;
    int lane = t & 31, wid = t >> 5;

    if (b == 0) {  // init scratch
        g_Ci[t] = 0.f; g_Ci[t + HN] = 0.f;
        if (t == 0) { g_sumexp = 0.f; g_vsum = 0.f; g_bar = 0; g_ticket = 0; }
    }

    // Ua convert: 64 blocks x 2048 elems
    {
        int base = b * 2048 + t * 8;
        float4 v0 = *reinterpret_cast<const float4*>(Uaw + base);
        float4 v1 = *reinterpret_cast<const float4*>(Uaw + base + 4);
        uint4 o;
        o.x = pkbf(v0.x, v0.y); o.y = pkbf(v0.z, v0.w);
        o.z = pkbf(v1.x, v1.y); o.w = pkbf(v1.z, v1.w);
        *reinterpret_cast<uint4*>(g_Ua16 + base) = o;
    }

    // Wa GEMV: warp per row, rows 0..255 over 512 warps
    int row = b * 8 + wid;
    if (row < HN) {
        const float4* w4 = reinterpret_cast<const float4*>(Waw + (size_t)row * HN);
        const float4* h4 = reinterpret_cast<const float4*>(hidden);
        float4 a0 = w4[lane], b0 = h4[lane], a1 = w4[lane + 32], b1 = h4[lane + 32];
        float v = a0.x * b0.x + a0.y * b0.y + a0.z * b0.z + a0.w * b0.w
                + a1.x * b1.x + a1.y * b1.y + a1.z * b1.z + a1.w * b1.w;
        v = warpSum(v);
        if (lane == 0) g_a[row] = v + Wab[row] + Uab[row];
    }
}

// ---------------- K_mega: persistent kernel, everything else ----------------
__global__ void __launch_bounds__(256) k_mega(
        const int* __restrict__ tok, const float* __restrict__ emb,
        const float* __restrict__ hidden, const float* __restrict__ enc,
        const float* __restrict__ Vaw, const float* __restrict__ Vab,
        const float* __restrict__ Uzw, const float* __restrict__ Uzb,
        const float* __restrict__ Urw, const float* __restrict__ Urb,
        const float* __restrict__ Uhw, const float* __restrict__ Uhb,
        const float* __restrict__ Wzw, const float* __restrict__ Wzb,
        const float* __restrict__ Wrw, const float* __restrict__ Wrb,
        const float* __restrict__ Czw, const float* __restrict__ Czb,
        const float* __restrict__ Crw, const float* __restrict__ Crb,
        const float* __restrict__ Whw, const float* __restrict__ Whb,
        const float* __restrict__ Chw, const float* __restrict__ Chb,
        const float* __restrict__ Vw,  const float* __restrict__ Vb,
        float* __restrict__ out, float* __restrict__ out_hidden,
        float* __restrict__ aij) {
    extern __shared__ __align__(16) char dsm[];
    __nv_bfloat16* s_encb = reinterpret_cast<__nv_bfloat16*>(dsm);          // 32 x LDE
    __nv_bfloat16* Bs     = reinterpret_cast<__nv_bfloat16*>(dsm + ENCB);   // 2 x BSZ
    float*         sy     = reinterpret_cast<float*>(dsm + ENCB + 2 * BSZ); // emb row, VN floats

    __shared__ float sE[32];
    __shared__ float s_ex[32];
    __shared__ float sred[8];
    __shared__ int   s_ticket;
    __shared__ __align__(16) float sh2[HN];
    __shared__ float s_vsum;

    int bid = blockIdx.x, t = threadIdx.x;
    int lane = t & 31, wid = t >> 5;

    unsigned encb_base = (unsigned)__cvta_generic_to_shared(s_encb);
    unsigned bs_base   = (unsigned)__cvta_generic_to_shared(Bs);

    // stage emb row y into smem once per CTA (reused by all U-GEMV tickets)
    {
        const float4* y = reinterpret_cast<const float4*>(emb + (size_t)tok[0] * VN);
        float4* d = reinterpret_cast<float4*>(sy);
#pragma unroll
        for (int i = t; i < VN / 4; i += 256) d[i] = y[i];
    }

    // ======================= PHASE A: ticket work pool =======================
    // tickets 0..127: attention tiles (32 s-rows)   128..895: U-GEMV rows
    for (;;) {
        __syncthreads();
        if (t == 0) s_ticket = atomicAdd(&g_ticket, 1);
        __syncthreads();
        int w = s_ticket;
        if (w >= 896) break;

        if (w >= 128) {
            // ---- U GEMV: g_u[g*HN+h] = U[h,:] . y + b   (y from smem) ----
            int idx = w - 128, g = idx >> 8, h = idx & 255;
            const float* W = (g == 0) ? Uzw : ((g == 1) ? Urw : Uhw);
            const float* B = (g == 0) ? Uzb : ((g == 1) ? Urb : Uhb);
            const float4* wv = reinterpret_cast<const float4*>(W + (size_t)h * VN);
            const float4* yv = reinterpret_cast<const float4*>(sy);
            float v = 0.f;
#pragma unroll
            for (int i = 0; i < VN / 4; i += 256) {
                float4 a = wv[i + t], c = yv[i + t];
                v = fmaf(a.x, c.x, fmaf(a.y, c.y, fmaf(a.z, c.z, fmaf(a.w, c.w, v))));
            }
            float r = blockSum256(v, sred);
            if (t == 0) g_u[g * HN + h] = r + B[h];
            continue;
        }

        // ---- attention tile: 32 s-rows via bf16 MMA (+ unnormalized Ci partial)
        int s0 = w * 32;
        int sg = wid & 1;        // s-group (16 rows)
        int hg = wid >> 1;       // h-group (64 cols)
        if (t < 32) sE[t] = 0.f;

        // kick off Bs chunk 0 (KC=64 -> 128B per row) via cp.async
        {
            const char* src = (const char*)(g_Ua16 + (size_t)t * 512);
            unsigned dst = bs_base + t * (LDA * 2);
#pragma unroll
            for (int q = 0; q < 8; q++) cp16(dst + q * 16, src + q * 16);
            asm volatile("cp.async.commit_group;");
        }

        // load + convert the full 32x512 enc tile into smem bf16 (once per tile)
        {
            int row = t >> 3, c0 = (t & 7) * 64;
            const float4* ev = reinterpret_cast<const float4*>(
                enc + (size_t)(s0 + row) * 512 + c0);
            __nv_bfloat16* dst = s_encb + row * LDE + c0;
#pragma unroll
            for (int j = 0; j < 4; j++) {
                float4 a = ev[4 * j], b2 = ev[4 * j + 1], c = ev[4 * j + 2], d = ev[4 * j + 3];
                uint4 o1, o2;
                o1.x = pkbf(a.x, a.y);  o1.y = pkbf(a.z, a.w);
                o1.z = pkbf(b2.x, b2.y); o1.w = pkbf(b2.z, b2.w);
                o2.x = pkbf(c.x, c.y);  o2.y = pkbf(c.z, c.w);
                o2.z = pkbf(d.x, d.y);  o2.w = pkbf(d.z, d.w);
                *reinterpret_cast<uint4*>(dst + 16 * j)     = o1;
                *reinterpret_cast<uint4*>(dst + 16 * j + 8) = o2;
            }
        }

        float acc[8][4];
#pragma unroll
        for (int nt = 0; nt < 8; nt++)
#pragma unroll
            for (int j = 0; j < 4; j++) acc[nt][j] = 0.f;

        unsigned a_addr = encb_base + ((sg * 16 + (lane & 15)) * LDE + (lane >> 4) * 8) * 2;
        unsigned b_base = bs_base + ((hg * 64 + (lane & 15)) * LDA + (lane >> 4) * 8) * 2;

        __syncthreads();   // enc tile staged

        int buf = 0;
        for (int kb = 0; kb < 512; kb += KC, buf ^= 1) {
            if (kb + KC < 512) {   // issue next Bs chunk into other buffer
                const char* src = (const char*)(g_Ua16 + (size_t)t * 512 + kb + KC);
                unsigned dst = bs_base + (buf ^ 1) * BSZ + t * (LDA * 2);
#pragma unroll
                for (int q = 0; q < 8; q++) cp16(dst + q * 16, src + q * 16);
                asm volatile("cp.async.commit_group;");
                asm volatile("cp.async.wait_group 1;");   // current chunk done
            } else {
                asm volatile("cp.async.wait_group 0;");
            }
            __syncthreads();       // Bs[buf] visible to all warps
            unsigned b_addr = b_base + buf * BSZ;
#pragma unroll
            for (int ks = 0; ks < 4; ks++) {              // 4 x k16 per 64-chunk
                unsigned a0, a1, a2, a3;
                ldm_x4(a0, a1, a2, a3, a_addr + (kb + ks * 16) * 2);
#pragma unroll
                for (int ntp = 0; ntp < 4; ntp++) {
                    unsigned r0, r1, r2, r3;
                    ldm_x4(r0, r1, r2, r3, b_addr + ntp * 16 * LDA * 2 + ks * 32);
                    mma_bf16(acc[2 * ntp],     a0, a1, a2, a3, r0, r2);
                    mma_bf16(acc[2 * ntp + 1], a0, a1, a2, a3, r1, r3);
                }
            }
            __syncthreads();       // all consumed Bs[buf] before overwrite
        }

        {   // epilogue: E[s] partials = sum_h Va[h]*tanh(P + g_a[h])
            int g = lane >> 2, tig = lane & 3;
            float p0 = 0.f, p1 = 0.f;
#pragma unroll
            for (int nt = 0; nt < 8; nt++) {
                int c0 = hg * 64 + nt * 8 + 2 * tig;
                float ga0 = g_a[c0], ga1 = g_a[c0 + 1];
                float va0 = Vaw[c0], va1 = Vaw[c0 + 1];
                p0 += va0 * tanh_fast(acc[nt][0] + ga0) + va1 * tanh_fast(acc[nt][1] + ga1);
                p1 += va0 * tanh_fast(acc[nt][2] + ga0) + va1 * tanh_fast(acc[nt][3] + ga1);
            }
            p0 += __shfl_xor_sync(0xffffffffu, p0, 1); p0 += __shfl_xor_sync(0xffffffffu, p0, 2);
            p1 += __shfl_xor_sync(0xffffffffu, p1, 1); p1 += __shfl_xor_sync(0xffffffffu, p1, 2);
            if (tig == 0) {
                atomicAdd(&sE[sg * 16 + g], p0);
                atomicAdd(&sE[sg * 16 + g + 8], p1);
            }
        }
        __syncthreads();
        float ex = 0.f;
        if (t < 32) {
            ex = expf(sE[t] + Vab[0]);          // |E| <~ 5: no max needed
            g_expE[s0 + t] = ex;
            s_ex[t] = ex;
        }
        if (wid == 0) {
            float v = warpSum(ex);
            if (lane == 0) atomicAdd(&g_sumexp, v);
        }
        __syncthreads();
        {   // unnormalized Ci partial: thread t handles cols {2t,2t+1} (float2, L2-hot)
            const float2* ep = reinterpret_cast<const float2*>(enc + (size_t)s0 * 512) + t;
            float a0 = 0.f, a1 = 0.f;
#pragma unroll 8
            for (int i = 0; i < 32; i++) {
                float e = s_ex[i];
                float2 v = ep[i * 256];
                a0 = fmaf(e, v.x, a0);
                a1 = fmaf(e, v.y, a1);
            }
            atomicAdd(&g_Ci[2 * t], a0);
            atomicAdd(&g_Ci[2 * t + 1], a1);
        }
    }

    // prefetch phase C/D/E weights into L2 while stragglers finish
    pf_range((const char*)Vw,  (size_t)VN * HN * 4, bid, t);
    pf_range((const char*)Czw, (size_t)HN * 512 * 4, bid, t);
    pf_range((const char*)Crw, (size_t)HN * 512 * 4, bid, t);
    pf_range((const char*)Chw, (size_t)HN * 512 * 4, bid, t);
    pf_range((const char*)Whw, (size_t)HN * HN * 4, bid, t);
    pf_range((const char*)Wzw, (size_t)HN * HN * 4, bid, t);
    pf_range((const char*)Wrw, (size_t)HN * HN * 4, bid, t);

    gsync(1);

    // ======================= PHASE C: z,r gates + aij ========================
    float inv = 1.0f / g_sumexp;
    {
        int gw = bid * 8 + wid;                  // warp per row, rows 0..511
        if (gw < 2 * HN) {
            int g = gw >> 8, h = gw & 255;
            const float* C  = g ? Crw : Czw;
            const float* Cb = g ? Crb : Czb;
            const float* W  = g ? Wrw : Wzw;
            const float* Wb = g ? Wrb : Wzb;
            const float4* c4  = reinterpret_cast<const float4*>(C + (size_t)h * 512);
            const float4* ci4 = reinterpret_cast<const float4*>(g_Ci);
            float vc = 0.f;
#pragma unroll
            for (int j = 0; j < 4; j++) {
                float4 a = c4[lane + 32 * j], c = ci4[lane + 32 * j];
                vc = fmaf(a.x, c.x, fmaf(a.y, c.y, fmaf(a.z, c.z, fmaf(a.w, c.w, vc))));
            }
            const float4* w4 = reinterpret_cast<const float4*>(W + (size_t)h * HN);
            const float4* h4 = reinterpret_cast<const float4*>(hidden);
            float vw = 0.f;
#pragma unroll
            for (int j = 0; j < 2; j++) {
                float4 a = w4[lane + 32 * j], c = h4[lane + 32 * j];
                vw = fmaf(a.x, c.x, fmaf(a.y, c.y, fmaf(a.z, c.z, fmaf(a.w, c.w, vw))));
            }
            float v = warpSum(vc * inv + vw);
            if (lane == 0) {
                float x = v + g_u[gw] + Cb[h] + Wb[h];
                g_zr[gw] = 1.f / (1.f + expf(-x));
            }
        }
        int idx = bid * 256 + t;                 // aij = expE / sumexp
        if (idx < SN) aij[idx] = g_expE[idx] * inv;
    }
    gsync(2);

    // ======================= PHASE D: candidate + hidden_new =================
    {
        int h = bid * 8 + wid;                   // warp per row, rows 0..255
        if (h < HN) {
            const float4* wh4 = reinterpret_cast<const float4*>(Whw + (size_t)h * HN);
            const float4* ch4 = reinterpret_cast<const float4*>(Chw + (size_t)h * 512);
            const float4* zr4 = reinterpret_cast<const float4*>(g_zr);
            const float4* hh4 = reinterpret_cast<const float4*>(hidden);
            const float4* ci4 = reinterpret_cast<const float4*>(g_Ci);
            float vw = 0.f, vc = 0.f;
#pragma unroll
            for (int j = 0; j < 2; j++) {
                float4 a = wh4[lane + 32 * j];
                float4 r = zr4[64 + lane + 32 * j];   // r gate = g_zr[256..511]
                float4 hh = hh4[lane + 32 * j];
                vw = fmaf(a.x, r.x * hh.x, fmaf(a.y, r.y * hh.y,
                     fmaf(a.z, r.z * hh.z, fmaf(a.w, r.w * hh.w, vw))));
            }
#pragma unroll
            for (int j = 0; j < 4; j++) {
                float4 a = ch4[lane + 32 * j], c = ci4[lane + 32 * j];
                vc = fmaf(a.x, c.x, fmaf(a.y, c.y, fmaf(a.z, c.z, fmaf(a.w, c.w, vc))));
            }
            float v = warpSum(vw + vc * inv);
            if (lane == 0) {
                float c = tanhf(v + g_u[2 * HN + h] + Whb[h] + Chb[h]);
                float z = g_zr[h];
                float hn = (1.f - z) * c + z * hidden[h];
                g_hid[h] = hn;
                out_hidden[h] = hn;
            }
        }
    }
    gsync(3);

    // ======================= PHASE E: vocab logits + vsum (2 rows/warp) =====
    sh2[t] = g_hid[t];
    if (t == 0) s_vsum = 0.f;
    __syncthreads();
    for (int row = bid * 16 + wid * 2; row < VN; row += gridDim.x * 16) {
        const float4* wa = reinterpret_cast<const float4*>(Vw + (size_t)row * HN);
        const float4* wb = reinterpret_cast<const float4*>(Vw + (size_t)(row + 1) * HN);
        const float4* hv = reinterpret_cast<const float4*>(sh2);
        float4 h0 = hv[lane], h1 = hv[lane + 32];
        float4 a0 = wa[lane], a1 = wa[lane + 32];
        float4 b0 = wb[lane], b1 = wb[lane + 32];
        float va = a0.x * h0.x + a0.y * h0.y + a0.z * h0.z + a0.w * h0.w
                 + a1.x * h1.x + a1.y * h1.y + a1.z * h1.z + a1.w * h1.w;
        float vb = b0.x * h0.x + b0.y * h0.y + b0.z * h0.z + b0.w * h0.w
                 + b1.x * h1.x + b1.y * h1.y + b1.z * h1.z + b1.w * h1.w;
        va = warpSum(va);
        vb = warpSum(vb);
        if (lane == 0) {
            float la = va + Vb[row], lb = vb + Vb[row + 1];
            g_logits[row] = la;
            g_logits[row + 1] = lb;
            atomicAdd(&s_vsum, expf(la) + expf(lb));   // |logit| small: no max needed
        }
    }
    __syncthreads();
    if (t == 0) atomicAdd(&g_vsum, s_vsum);
    gsync(4);

    // ======================= PHASE F: out = logits - lse =====================
    {
        float lse = logf(g_vsum);
        int i = bid * 256 + t;
        if (i < VN) out[i] = g_logits[i] - lse;
    }
}

// ---------------------------------------------------------------------------
extern "C" void kernel_launch(void* const* d_in, const int* in_sizes, int n_in,
                              void* d_out, int out_size) {
    (void)in_sizes; (void)n_in; (void)out_size;
    const int*   tok    = (const int*)  d_in[0];
    const float* hidden = (const float*)d_in[1];
    const float* enc    = (const float*)d_in[2];
    const float* emb    = (const float*)d_in[3];
    const float *Uzw = (const float*)d_in[4],  *Uzb = (const float*)d_in[5];
    const float *Wzw = (const float*)d_in[6],  *Wzb = (const float*)d_in[7];
    const float *Czw = (const float*)d_in[8],  *Czb = (const float*)d_in[9];
    const float *Urw = (const float*)d_in[10], *Urb = (const float*)d_in[11];
    const float *Wrw = (const float*)d_in[12], *Wrb = (const float*)d_in[13];
    const float *Crw = (const float*)d_in[14], *Crb = (const float*)d_in[15];
    const float *Uhw = (const float*)d_in[16], *Uhb = (const float*)d_in[17];
    const float *Whw = (const float*)d_in[18], *Whb = (const float*)d_in[19];
    const float *Chw = (const float*)d_in[20], *Chb = (const float*)d_in[21];
    const float *Uaw = (const float*)d_in[22], *Uab = (const float*)d_in[23];
    const float *Waw = (const float*)d_in[24], *Wab = (const float*)d_in[25];
    const float *Vaw = (const float*)d_in[26], *Vab = (const float*)d_in[27];
    const float *Vw  = (const float*)d_in[28], *Vb  = (const float*)d_in[29];

    float* out        = (float*)d_out;       // [VN] log_softmax
    float* out_hidden = out + VN;            // [HN] hidden_new
    float* aij        = out + VN + HN;       // [SN] attention weights

    // host-side config: runs once at capture time, free at graph replay
    static int grid = 0;
    if (grid == 0) {
        cudaFuncSetAttribute(k_mega, cudaFuncAttributeMaxDynamicSharedMemorySize, DSM_BYTES);
        int dev = 0; cudaGetDevice(&dev);
        int sms = 148;
        cudaDeviceGetAttribute(&sms, cudaDevAttrMultiProcessorCount, dev);
        grid = sms;               // EXACTLY 1 CTA/SM: empirically the best config
    }

    k_pre<<<64, 256>>>(hidden, Waw, Wab, Uab, Uaw);
    k_mega<<<grid, 256, DSM_BYTES>>>(tok, emb, hidden, enc, Vaw, Vab,
                                     Uzw, Uzb, Urw, Urb, Uhw, Uhb,
                                     Wzw, Wzb, Wrw, Wrb,
                                     Czw, Czb, Crw, Crb,
                                     Whw, Whb, Chw, Chb,
                                     Vw, Vb, out, out_hidden, aij);
}